// round 6
// baseline (speedup 1.0000x reference)
#include <cuda_runtime.h>

// Ping-pong scratch (device globals — no allocation allowed).
__device__ float g_buf1[4 * 3 * 96  * 128];   // stage1 out
__device__ float g_buf2[4 * 3 * 192 * 256];   // stage2 out
__device__ float g_buf3[4 * 3 * 384 * 512];   // stage3 out

// One convex-upsample stage (scale=2). Thread = one SOURCE pixel (n,h,w),
// producing the 2x2 output quad for all 3 channels.
// mask layout [N,36,H,W], channel c = k*4 + i*2 + j (k: 3x3 tap, i,j: subpixel).
// Softmax over k without max-subtraction (exp of ~N(0,1) is safe; identical result).
// H/W compile-time so all 36 mask offsets + strides constant-fold.
// TPB/MINB: per-stage block size + occupancy target (small stages need more CTAs).
template<int H, int WSHIFT, bool FIRST, int TPB, int MINB>
__global__ __launch_bounds__(TPB, MINB)
void convex_up_quad(const float* __restrict__ in_flow,
                    const float* __restrict__ in_dz,
                    const float* __restrict__ mask,
                    float* __restrict__ out)
{
    constexpr int W  = 1 << WSHIFT;
    constexpr int HW = H * W;

    const int idx = blockIdx.x * TPB + threadIdx.x;   // grid is exact: no guard
    const int n = blockIdx.y;
    const int w = idx & (W - 1);
    const int h = idx >> WSHIFT;

    const float* mb = mask + (size_t)n * (36 * HW) + idx;   // + c*HW per channel
    const float* pf = in_flow + (size_t)n * (FIRST ? 2 * HW : 3 * HW);
    const float* pd = in_dz   + (size_t)n * (FIRST ?     HW : 3 * HW);

    float sum[4];
    float acc[4][3];
#pragma unroll
    for (int q = 0; q < 4; q++) {
        sum[q] = 0.f;
        acc[q][0] = acc[q][1] = acc[q][2] = 0.f;
    }

#pragma unroll
    for (int k = 0; k < 9; k++) {
        const int dy = k / 3 - 1;
        const int dx = k % 3 - 1;
        const int hh = h + dy;
        const int ww = w + dx;
        const bool ok = (hh >= 0) && (hh < H) && (ww >= 0) && (ww < W);
        float v0 = 0.f, v1 = 0.f, v2 = 0.f;
        if (ok) {
            const int off = (hh << WSHIFT) + ww;
            v0 = pf[off];
            v1 = pf[off + HW];
            v2 = pd[off];
        }
#pragma unroll
        for (int q = 0; q < 4; q++) {
            float e = __expf(__ldcs(mb + (size_t)(k * 4 + q) * HW));
            sum[q] += e;
            acc[q][0] = fmaf(e, v0, acc[q][0]);
            acc[q][1] = fmaf(e, v1, acc[q][1]);
            acc[q][2] = fmaf(e, v2, acc[q][2]);
        }
    }

    float inv[4];
#pragma unroll
    for (int q = 0; q < 4; q++) inv[q] = __fdividef(1.0f, sum[q]);

    // out [N,3,2H,2W]; quad q = i*2+j -> pixel (2h+i, 2w+j). float2 stores.
    constexpr int W2 = W << 1;
    constexpr size_t HW4 = (size_t)HW * 4;
    float* ob = out + (size_t)n * (3 * HW4)
                    + ((size_t)h << (WSHIFT + 2)) + (w << 1);
#pragma unroll
    for (int ch = 0; ch < 3; ch++) {
        const float pm = (ch < 2) ? 2.0f : 1.0f;   // flow premul per stage
#pragma unroll
        for (int i = 0; i < 2; i++) {
            float2 v;
            v.x = pm * acc[i * 2 + 0][ch] * inv[i * 2 + 0];
            v.y = pm * acc[i * 2 + 1][ch] * inv[i * 2 + 1];
            *reinterpret_cast<float2*>(ob + (size_t)ch * HW4 + (size_t)i * W2) = v;
        }
    }
}

template<int H, int WSHIFT, bool FIRST, int TPB, int MINB>
static inline void launch_stage(const float* pf, const float* pd,
                                const float* mask, float* out, int N)
{
    constexpr int HW = H << WSHIFT;
    static_assert(HW % TPB == 0, "exact grid");
    dim3 grid(HW / TPB, N);
    convex_up_quad<H, WSHIFT, FIRST, TPB, MINB><<<grid, TPB>>>(pf, pd, mask, out);
}

extern "C" void kernel_launch(void* const* d_in, const int* in_sizes, int n_in,
                              void* d_out, int out_size)
{
    const float* flow16 = (const float*)d_in[0];  // [4,2,48,64]
    const float* dz16   = (const float*)d_in[1];  // [4,1,48,64]
    const float* mask16 = (const float*)d_in[2];  // [4,36,48,64]
    const float* mask8  = (const float*)d_in[3];  // [4,36,96,128]
    const float* mask4  = (const float*)d_in[4];  // [4,36,192,256]
    const float* mask2  = (const float*)d_in[5];  // [4,36,384,512]
    float* out = (float*)d_out;                   // [4,3,768,1024]

    float *buf1, *buf2, *buf3;
    cudaGetSymbolAddress((void**)&buf1, g_buf1);
    cudaGetSymbolAddress((void**)&buf2, g_buf2);
    cudaGetSymbolAddress((void**)&buf3, g_buf3);

    const int N = 4;

    // Stage 1: 48x64 -> 96x128. 64-thr blocks -> 192 CTAs (fill the chip).
    launch_stage<48, 6, true, 64, 8>(flow16, dz16, mask16, buf1, N);
    // Stage 2: 96x128 -> 192x256. 64-thr blocks -> 768 CTAs.
    launch_stage<96, 7, false, 64, 8>(buf1, buf1 + 2 * 96 * 128, mask8, buf2, N);
    // Stage 3: 192x256 -> 384x512. Control: same config as R4.
    launch_stage<192, 8, false, 256, 5>(buf2, buf2 + 2 * 192 * 256, mask4, buf3, N);
    // Stage 4: 384x512 -> 768x1024. Experiment: occupancy 6 blocks/SM.
    launch_stage<384, 9, false, 256, 6>(buf3, buf3 + 2 * 384 * 512, mask2, out, N);
}

// round 7
// speedup vs baseline: 1.2228x; 1.2228x over previous
#include <cuda_runtime.h>

// Ping-pong scratch (device globals — no allocation allowed).
__device__ float g_buf1[4 * 3 * 96  * 128];   // stage1 out
__device__ float g_buf2[4 * 3 * 192 * 256];   // stage2 out
__device__ float g_buf3[4 * 3 * 384 * 512];   // stage3 out

// One convex-upsample stage (scale=2). Thread = one SOURCE pixel (n,h,w),
// producing the 2x2 output quad for all 3 channels.
// mask layout [N,36,H,W], channel c = k*4 + i*2 + j (k: 3x3 tap, i,j: subpixel).
// Softmax over k without max-subtraction (exp of ~N(0,1) is safe; identical result).
// H/W compile-time so all 36 mask offsets + strides constant-fold.
template<int H, int WSHIFT, bool FIRST, int TPB, int MINB>
__global__ __launch_bounds__(TPB, MINB)
void convex_up_quad(const float* __restrict__ in_flow,
                    const float* __restrict__ in_dz,
                    const float* __restrict__ mask,
                    float* __restrict__ out)
{
    constexpr int W  = 1 << WSHIFT;
    constexpr int HW = H * W;

    const int idx = blockIdx.x * TPB + threadIdx.x;   // grid is exact: no guard
    const int n = blockIdx.y;
    const int w = idx & (W - 1);
    const int h = idx >> WSHIFT;

    const float* mb = mask + (size_t)n * (36 * HW) + idx;   // + c*HW per channel
    const float* pf = in_flow + (size_t)n * (FIRST ? 2 * HW : 3 * HW);
    const float* pd = in_dz   + (size_t)n * (FIRST ?     HW : 3 * HW);

    // Hoisted edge predicates / row validity (live in predicate regs).
    const bool okl = (w > 0), okr = (w + 1 < W);
    const bool oku = (h > 0), okd = (h + 1 < H);

    float sum[4];
    float acc[4][3];
#pragma unroll
    for (int q = 0; q < 4; q++) {
        sum[q] = 0.f;
        acc[q][0] = acc[q][1] = acc[q][2] = 0.f;
    }

#pragma unroll
    for (int k = 0; k < 9; k++) {
        const int dy = k / 3 - 1;
        const int dx = k % 3 - 1;
        const bool ok = (dy == 0 || (dy < 0 ? oku : okd)) &&
                        (dx == 0 || (dx < 0 ? okl : okr));
        float v0 = 0.f, v1 = 0.f, v2 = 0.f;
        if (ok) {
            const int off = ((h + dy) << WSHIFT) + (w + dx);
            v0 = pf[off];
            v1 = pf[off + HW];
            v2 = pd[off];
        }
#pragma unroll
        for (int q = 0; q < 4; q++) {
            float e = __expf(__ldcs(mb + (size_t)(k * 4 + q) * HW));
            sum[q] += e;
            acc[q][0] = fmaf(e, v0, acc[q][0]);
            acc[q][1] = fmaf(e, v1, acc[q][1]);
            acc[q][2] = fmaf(e, v2, acc[q][2]);
        }
    }

    float inv[4];
#pragma unroll
    for (int q = 0; q < 4; q++) inv[q] = __fdividef(1.0f, sum[q]);

    // out [N,3,2H,2W]; quad q = i*2+j -> pixel (2h+i, 2w+j). float2 stores.
    constexpr int W2 = W << 1;
    constexpr size_t HW4 = (size_t)HW * 4;
    float* ob = out + (size_t)n * (3 * HW4)
                    + ((size_t)h << (WSHIFT + 2)) + (w << 1);
#pragma unroll
    for (int ch = 0; ch < 3; ch++) {
        const float pm = (ch < 2) ? 2.0f : 1.0f;   // flow premul per stage
#pragma unroll
        for (int i = 0; i < 2; i++) {
            float2 v;
            v.x = pm * acc[i * 2 + 0][ch] * inv[i * 2 + 0];
            v.y = pm * acc[i * 2 + 1][ch] * inv[i * 2 + 1];
            *reinterpret_cast<float2*>(ob + (size_t)ch * HW4 + (size_t)i * W2) = v;
        }
    }
}

template<int H, int WSHIFT, bool FIRST, int TPB, int MINB>
static inline void launch_stage(const float* pf, const float* pd,
                                const float* mask, float* out, int N)
{
    constexpr int HW = H << WSHIFT;
    static_assert(HW % TPB == 0, "exact grid");
    dim3 grid(HW / TPB, N);
    convex_up_quad<H, WSHIFT, FIRST, TPB, MINB><<<grid, TPB>>>(pf, pd, mask, out);
}

extern "C" void kernel_launch(void* const* d_in, const int* in_sizes, int n_in,
                              void* d_out, int out_size)
{
    const float* flow16 = (const float*)d_in[0];  // [4,2,48,64]
    const float* dz16   = (const float*)d_in[1];  // [4,1,48,64]
    const float* mask16 = (const float*)d_in[2];  // [4,36,48,64]
    const float* mask8  = (const float*)d_in[3];  // [4,36,96,128]
    const float* mask4  = (const float*)d_in[4];  // [4,36,192,256]
    const float* mask2  = (const float*)d_in[5];  // [4,36,384,512]
    float* out = (float*)d_out;                   // [4,3,768,1024]

    float *buf1, *buf2, *buf3;
    cudaGetSymbolAddress((void**)&buf1, g_buf1);
    cudaGetSymbolAddress((void**)&buf2, g_buf2);
    cudaGetSymbolAddress((void**)&buf3, g_buf3);

    const int N = 4;

    // Stage 1: 48x64 -> 96x128. 64-thr blocks -> 192 CTAs (fill the chip).
    launch_stage<48, 6, true, 64, 8>(flow16, dz16, mask16, buf1, N);
    // Stage 2: 96x128 -> 192x256. 64-thr blocks -> 768 CTAs.
    launch_stage<96, 7, false, 64, 8>(buf1, buf1 + 2 * 96 * 128, mask8, buf2, N);
    // Stage 3: 192x256 -> 384x512. Proven config (R4).
    launch_stage<192, 8, false, 256, 5>(buf2, buf2 + 2 * 192 * 256, mask4, buf3, N);
    // Stage 4: 384x512 -> 768x1024. REVERTED to proven (256, 5) — (256,6) spilled.
    launch_stage<384, 9, false, 256, 5>(buf3, buf3 + 2 * 384 * 512, mask2, out, N);
}